// round 15
// baseline (speedup 1.0000x reference)
#include <cuda_runtime.h>
#include <cuda_fp16.h>
#include <cstdint>

// LSTM decoder on mma.sync m16n8k16 + ldmatrix (compute_100-safe).
// One persistent CTA per SM (148), 256 threads (8 warps), batch slice 14 (N=16 pad).
// gates[512x16] = Wc[512x128] @ h^T, fp32 register accum, separate accumulator
// chains per precision pass (hi@Bhi / hi@Blo / lo@Bhi) for 2x MMA ILP.
// Precision: h = hhi+hlo; f,g: A-hi@(Bhi+Blo) + A-lo@Bhi; i,o: A-hi@Bhi only;
// Wo: hi@(Bhi+Blo). Out-GEMM split into 8 tasks (4 row-tiles x 2 n-halves),
// one per warp -> perfectly balanced 144 MMA/warp/step.
// Identity: x_t == h_t for t>=1 => Wc = W_ih + W_hh. Step 0 runs the same MMA
// path with A = W_hh, then A is rewritten with Wc.

#define Tq 512
#define Oq 64
#define Lq 64

// SMEM byte offsets. A regions: [rows][128 k] fp16, 256B/row, XOR-swizzled.
#define A_HI   0u        // 512 rows (4 gate tiles of 128 rows)     131072 B
#define A_GLO  131072u   // 128 rows: g-gate lo                      32768 B
#define A_FLO  163840u   // 128 rows: f-gate lo                      32768 B
#define A_WO   196608u   // 64 rows: Wo hi                           16384 B
#define H_HI   212992u   // h hi: [16 n][128 k] fp16, 272B row stride 4352 B
#define H_LO   217344u   // h lo                                      4352 B
#define SMEM_BYTES 221696u
#define HSTB   272u

// ---------- helpers ----------
__device__ __forceinline__ unsigned sm_u32(const void* p) {
    unsigned r;
    asm("{ .reg .u64 t; cvta.to.shared.u64 t, %1; cvt.u32.u64 %0, t; }" : "=r"(r) : "l"(p));
    return r;
}
__device__ __forceinline__ float sigf(float x)   { return __fdividef(1.f, 1.f + __expf(-x)); }
__device__ __forceinline__ float tanhf2(float x) { return __fdividef(2.f, 1.f + __expf(-2.f * x)) - 1.f; }

// Swizzle: o ^ ((row&7)<<4). Keeps 16B segments intact; ldmatrix conflict-free.
__device__ __forceinline__ unsigned aswz(unsigned o) { return o ^ ((o >> 4) & 0x70u); }

__device__ __forceinline__ void ldmx4(unsigned* a, unsigned addr) {
    asm volatile("ldmatrix.sync.aligned.m8n8.x4.shared.b16 {%0,%1,%2,%3}, [%4];"
        : "=r"(a[0]), "=r"(a[1]), "=r"(a[2]), "=r"(a[3]) : "r"(addr));
}
__device__ __forceinline__ void mma16(float* d, const unsigned* a, unsigned b0, unsigned b1) {
    asm volatile(
        "mma.sync.aligned.m16n8k16.row.col.f32.f16.f16.f32 "
        "{%0,%1,%2,%3}, {%4,%5,%6,%7}, {%8,%9}, {%0,%1,%2,%3};"
        : "+f"(d[0]), "+f"(d[1]), "+f"(d[2]), "+f"(d[3])
        : "r"(a[0]), "r"(a[1]), "r"(a[2]), "r"(a[3]), "r"(b0), "r"(b1));
}

// Fill A tiles from weights. comb=false: W_hh (step 0); true: W_ih+W_hh.
__device__ __forceinline__ void init_A(char* smc, const float* __restrict__ W_ih,
                                       const float* __restrict__ W_hh, int tid, bool comb) {
    for (int i = tid; i < 512 * 128; i += 256) {
        int r = i >> 7, k = i & 127;
        float v = W_hh[i];
        if (comb) v += W_ih[i];
        __half hh = __float2half(v);
        *(__half*)(smc + A_HI + aswz((unsigned)(r * 256 + k * 2))) = hh;
        int g = r >> 7, u = r & 127;
        if (g == 1)
            *(__half*)(smc + A_FLO + aswz((unsigned)(u * 256 + k * 2))) =
                __float2half(v - __half2float(hh));
        if (g == 2)
            *(__half*)(smc + A_GLO + aswz((unsigned)(u * 256 + k * 2))) =
                __float2half(v - __half2float(hh));
    }
}

__global__ void __launch_bounds__(256, 1) decoder_main(
    const float* __restrict__ latent, const float* __restrict__ fc_w, const float* __restrict__ fc_b,
    const float* __restrict__ W_ih,   const float* __restrict__ W_hh,
    const float* __restrict__ b_ih,   const float* __restrict__ b_hh,
    const float* __restrict__ Wo,     const float* __restrict__ bo,
    float* __restrict__ out)
{
    extern __shared__ char smc[];
    const unsigned smb = sm_u32(smc);
    const int tid = threadIdx.x, l = tid & 31, w = tid >> 5;
    const int cta = blockIdx.x;
    int bstart, nb;
    if (cta < 124) { bstart = cta * 14;                nb = 14; }
    else           { bstart = 1736 + (cta - 124) * 13; nb = 13; }

    // ---- init A with W_hh (step 0), Wo hi ----
    init_A(smc, W_ih, W_hh, tid, false);
    for (int i = tid; i < 64 * 128; i += 256) {
        int o = i >> 7, k = i & 127;
        *(__half*)(smc + A_WO + aswz((unsigned)(o * 256 + k * 2))) = __float2half(Wo[i]);
    }

    // ---- h0 = fc(latent), split hi/lo into B tiles (pad n -> 0) ----
    for (int i = tid; i < 2048; i += 256) {
        int k = i >> 4, n = i & 15;
        float a = 0.f;
        if (n < nb) {
            a = fc_b[k];
            const float* lp = latent + (size_t)(bstart + n) * Lq;
            const float* wp = fc_w + k * Lq;
#pragma unroll 8
            for (int j = 0; j < Lq; j++) a += lp[j] * wp[j];
        }
        __half hh = __float2half(a);
        *(__half*)(smc + H_HI + n * HSTB + k * 2) = hh;
        *(__half*)(smc + H_LO + n * HSTB + k * 2) = __float2half(a - __half2float(hh));
    }

    // ---- per-lane constants ----
    const int rr   = (l & 7) + ((l >> 3) & 1) * 8;      // ldmatrix row within 16
    const unsigned kxor = (unsigned)((l & 7) << 4);
    const unsigned kc0  = (unsigned)(((l >> 4) & 1) * 16);
    unsigned kbx[8];
#pragma unroll
    for (int kk = 0; kk < 8; kk++) kbx[kk] = ((unsigned)(kk * 32) + kc0) ^ kxor;

    unsigned rowA[4], rowGlo, rowFlo, rowWo;
#pragma unroll
    for (int g = 0; g < 4; g++)
        rowA[g] = smb + A_HI + (unsigned)((g * 128 + 16 * w + rr) * 256);
    rowGlo = smb + A_GLO + (unsigned)((16 * w + rr) * 256);
    rowFlo = smb + A_FLO + (unsigned)((16 * w + rr) * 256);
    // Out task: warp w -> Wo row-tile (w&3), n-half (w>>2).
    const int wrt = w & 3, nts = w >> 2;
    rowWo = smb + A_WO + (unsigned)((16 * wrt + rr) * 256);

    const int nlo = l >> 2;            // 0..7
    const int kof = (l & 3) * 4;       // bytes
    const char* bb0 = smc + H_HI + (0 * 8 + nlo) * HSTB + kof;
    const char* bb1 = smc + H_HI + (1 * 8 + nlo) * HSTB + kof;

    const int u0 = 16 * w + (l >> 2), u1 = u0 + 8;
    float bia[2][4];
#pragma unroll
    for (int g = 0; g < 4; g++) {
        bia[0][g] = b_ih[g * 128 + u0] + b_hh[g * 128 + u0];
        bia[1][g] = b_ih[g * 128 + u1] + b_hh[g * 128 + u1];
    }
    const int oo0 = 16 * wrt + (l >> 2), oo1 = oo0 + 8;
    const float bo0 = bo[oo0], bo1 = bo[oo1];
    const int nbase = 2 * (l & 3);
    float cS[8];
#pragma unroll
    for (int j = 0; j < 8; j++) cS[j] = 0.f;

    __syncthreads();

    // ---- main loop: iteration i uses B=h_i; gates -> h_{i+1}; out_{i-1} ----
    for (int i = 0; i < Tq; i++) {
        // load B fragments (hi & lo, 2 n-tiles x 8 k-steps)
        unsigned bh[2][8][2], bl[2][8][2];
#pragma unroll
        for (int kk = 0; kk < 8; kk++) {
            bh[0][kk][0] = *(const unsigned*)(bb0 + kk * 32);
            bh[0][kk][1] = *(const unsigned*)(bb0 + kk * 32 + 16);
            bh[1][kk][0] = *(const unsigned*)(bb1 + kk * 32);
            bh[1][kk][1] = *(const unsigned*)(bb1 + kk * 32 + 16);
            bl[0][kk][0] = *(const unsigned*)(bb0 + 4352 + kk * 32);
            bl[0][kk][1] = *(const unsigned*)(bb0 + 4352 + kk * 32 + 16);
            bl[1][kk][0] = *(const unsigned*)(bb1 + 4352 + kk * 32);
            bl[1][kk][1] = *(const unsigned*)(bb1 + 4352 + kk * 32 + 16);
        }

        // Separate accumulator chains (summed in elementwise):
        float Di[2][4], Dfa[2][4], Dfb[2][4], Dfc[2][4];
        float Dga[2][4], Dgb[2][4], Dgc[2][4], Do_[2][4];
        float Dwa[4], Dwb[4];
#pragma unroll
        for (int nt = 0; nt < 2; nt++)
#pragma unroll
            for (int q = 0; q < 4; q++) {
                Di[nt][q] = 0.f; Dfa[nt][q] = 0.f; Dfb[nt][q] = 0.f; Dfc[nt][q] = 0.f;
                Dga[nt][q] = 0.f; Dgb[nt][q] = 0.f; Dgc[nt][q] = 0.f; Do_[nt][q] = 0.f;
            }
#pragma unroll
        for (int q = 0; q < 4; q++) { Dwa[q] = 0.f; Dwb[q] = 0.f; }

#pragma unroll
        for (int kk = 0; kk < 8; kk++) {
            unsigned a[4];
            // i gate: hi@Bhi only
            ldmx4(a, rowA[0] + kbx[kk]);
            mma16(Di[0], a, bh[0][kk][0], bh[0][kk][1]);
            mma16(Di[1], a, bh[1][kk][0], bh[1][kk][1]);
            // f gate: hi@Bhi + hi@Blo
            ldmx4(a, rowA[1] + kbx[kk]);
            mma16(Dfa[0], a, bh[0][kk][0], bh[0][kk][1]);
            mma16(Dfa[1], a, bh[1][kk][0], bh[1][kk][1]);
            mma16(Dfb[0], a, bl[0][kk][0], bl[0][kk][1]);
            mma16(Dfb[1], a, bl[1][kk][0], bl[1][kk][1]);
            // f-lo @ Bhi
            ldmx4(a, rowFlo + kbx[kk]);
            mma16(Dfc[0], a, bh[0][kk][0], bh[0][kk][1]);
            mma16(Dfc[1], a, bh[1][kk][0], bh[1][kk][1]);
            // g gate: hi@Bhi + hi@Blo
            ldmx4(a, rowA[2] + kbx[kk]);
            mma16(Dga[0], a, bh[0][kk][0], bh[0][kk][1]);
            mma16(Dga[1], a, bh[1][kk][0], bh[1][kk][1]);
            mma16(Dgb[0], a, bl[0][kk][0], bl[0][kk][1]);
            mma16(Dgb[1], a, bl[1][kk][0], bl[1][kk][1]);
            // g-lo @ Bhi
            ldmx4(a, rowGlo + kbx[kk]);
            mma16(Dgc[0], a, bh[0][kk][0], bh[0][kk][1]);
            mma16(Dgc[1], a, bh[1][kk][0], bh[1][kk][1]);
            // o gate: hi@Bhi only
            ldmx4(a, rowA[3] + kbx[kk]);
            mma16(Do_[0], a, bh[0][kk][0], bh[0][kk][1]);
            mma16(Do_[1], a, bh[1][kk][0], bh[1][kk][1]);
            // out task: Wo hi @ (Bhi + Blo), single n-half nts
            ldmx4(a, rowWo + kbx[kk]);
            mma16(Dwa, a, bh[nts][kk][0], bh[nts][kk][1]);
            mma16(Dwb, a, bl[nts][kk][0], bl[nts][kk][1]);
        }
        __syncthreads();   // all B reads done before h overwrite

        // ---- elementwise: c,h update; split-store h_{i+1} ----
#pragma unroll
        for (int nt = 0; nt < 2; nt++)
#pragma unroll
            for (int q = 0; q < 4; q++) {
                int ui = q >> 1;
                int u  = ui ? u1 : u0;
                int n  = nt * 8 + nbase + (q & 1);
                float I = sigf(Di[nt][q] + bia[ui][0]);
                float F = sigf(Dfa[nt][q] + Dfb[nt][q] + Dfc[nt][q] + bia[ui][1]);
                float G = tanhf2(Dga[nt][q] + Dgb[nt][q] + Dgc[nt][q] + bia[ui][2]);
                float O = sigf(Do_[nt][q] + bia[ui][3]);
                float c = F * cS[nt * 4 + q] + I * G;
                cS[nt * 4 + q] = c;
                float h = O * tanhf2(c);
                __half hh = __float2half(h);
                __half hl = __float2half(h - __half2float(hh));
                *(__half*)(smc + H_HI + n * HSTB + u * 2) = hh;
                *(__half*)(smc + H_LO + n * HSTB + u * 2) = hl;
            }

        // ---- store out[i-1] (every warp has one out task) ----
        if (i > 0) {
#pragma unroll
            for (int q = 0; q < 4; q++) {
                int n = nts * 8 + nbase + (q & 1);
                int o = (q >> 1) ? oo1 : oo0;
                if (n < nb)
                    out[(((size_t)(bstart + n)) * Tq + (i - 1)) * Oq + o] =
                        Dwa[q] + Dwb[q] + ((q >> 1) ? bo1 : bo0);
            }
        }
        __syncthreads();

        // after step 0: rewrite A tiles with Wc = W_ih + W_hh
        if (i == 0) {
            init_A(smc, W_ih, W_hh, tid, true);
            __syncthreads();
        }
    }

    // ---- tail: out[T-1] = Wo @ h_T (same per-warp out task) ----
    {
        float Dwa[4], Dwb[4];
#pragma unroll
        for (int q = 0; q < 4; q++) { Dwa[q] = 0.f; Dwb[q] = 0.f; }
        const char* bbn = (nts == 0) ? bb0 : bb1;
#pragma unroll
        for (int kk = 0; kk < 8; kk++) {
            unsigned b0 = *(const unsigned*)(bbn + kk * 32);
            unsigned b1 = *(const unsigned*)(bbn + kk * 32 + 16);
            unsigned c0 = *(const unsigned*)(bbn + 4352 + kk * 32);
            unsigned c1 = *(const unsigned*)(bbn + 4352 + kk * 32 + 16);
            unsigned a[4];
            ldmx4(a, rowWo + kbx[kk]);
            mma16(Dwa, a, b0, b1);
            mma16(Dwb, a, c0, c1);
        }
#pragma unroll
        for (int q = 0; q < 4; q++) {
            int n = nts * 8 + nbase + (q & 1);
            int o = (q >> 1) ? oo1 : oo0;
            if (n < nb)
                out[(((size_t)(bstart + n)) * Tq + (Tq - 1)) * Oq + o] =
                    Dwa[q] + Dwb[q] + ((q >> 1) ? bo1 : bo0);
        }
    }
}

extern "C" void kernel_launch(void* const* d_in, const int* in_sizes, int n_in,
                              void* d_out, int out_size) {
    const float* latent = (const float*)d_in[0];
    const float* fc_w   = (const float*)d_in[1];
    const float* fc_b   = (const float*)d_in[2];
    const float* W_ih   = (const float*)d_in[3];
    const float* W_hh   = (const float*)d_in[4];
    const float* b_ih   = (const float*)d_in[5];
    const float* b_hh   = (const float*)d_in[6];
    const float* Wo     = (const float*)d_in[7];
    const float* bo     = (const float*)d_in[8];
    float* out = (float*)d_out;

    cudaFuncSetAttribute(decoder_main,
                         cudaFuncAttributeMaxDynamicSharedMemorySize, SMEM_BYTES);

    decoder_main<<<148, 256, SMEM_BYTES>>>(latent, fc_w, fc_b, W_ih, W_hh,
                                           b_ih, b_hh, Wo, bo, out);
}